// round 5
// baseline (speedup 1.0000x reference)
#include <cuda_runtime.h>
#include <math.h>

#define DIM_EI  4096
#define DIM_CA3 8192
#define DIM_CA1 8192
#define DIM_EO  4096

static constexpr float BETA  = 10.0f;
static constexpr float ALPHA = 0.01f;

// ---------------- device scratch ----------------
__device__ float g_h1[DIM_CA3];
__device__ float g_h3[DIM_CA1];
__device__ float g_h4[DIM_EO];
__device__ float g_xca3[DIM_CA3];
__device__ float g_IS[DIM_CA1];
__device__ float g_xca1[DIM_CA1];
__device__ int   g_nnz_idx[DIM_CA3];
__device__ float g_nnz_val[DIM_CA3];
__device__ int   g_nnz_cnt;
__device__ unsigned g_ctr_h1;   // arrival counters; self-reset by consumer
__device__ unsigned g_ctr_h3;
__device__ unsigned g_ctr_out;

// ---------------- helpers ----------------
__device__ __forceinline__ unsigned f2u(float f) {
    unsigned u = __float_as_uint(f);
    return (u & 0x80000000u) ? ~u : (u | 0x80000000u);
}
__device__ __forceinline__ float u2f(unsigned u) {
    return __uint_as_float((u & 0x80000000u) ? (u & 0x7fffffffu) : ~u);
}
__device__ __forceinline__ float sigm(float z) { return 1.0f / (1.0f + expf(-z)); }

// Exact K-th largest of x[0..n) via 4-pass radix-256; values re-read from
// global (L2-hot) each pass so callers carry no register burden.
// Requires blockDim.x == 256; all threads must call.
__device__ float kth_global_256(const float* __restrict__ x, int n, int K) {
    __shared__ unsigned s_hist[256];
    __shared__ int s_bin, s_k;
    int tid = threadIdx.x;
    unsigned prefix = 0;
    int k = K;
    #pragma unroll
    for (int shift = 24; shift >= 0; shift -= 8) {
        s_hist[tid] = 0;
        __syncthreads();
        unsigned hi = (shift == 24) ? 0u : (0xFFFFFFFFu << (shift + 8));
        for (int i = tid; i < n; i += 256) {
            unsigned u = f2u(x[i]);
            if ((u & hi) == prefix) atomicAdd(&s_hist[(u >> shift) & 255], 1u);
        }
        __syncthreads();
        #pragma unroll
        for (int d = 1; d < 256; d <<= 1) {
            unsigned add = (tid + d < 256) ? s_hist[tid + d] : 0u;
            __syncthreads();
            s_hist[tid] += add;
            __syncthreads();
        }
        {
            unsigned ge = s_hist[tid];
            unsigned gt = (tid == 255) ? 0u : s_hist[tid + 1];
            if (ge >= (unsigned)k && gt < (unsigned)k) { s_bin = tid; s_k = k - (int)gt; }
        }
        __syncthreads();
        prefix |= ((unsigned)s_bin) << shift;
        k = s_k;
        __syncthreads();
    }
    return u2f(prefix);
}

// ---------------- K1: fused dual matvec + stageA tails ----------------
// Blocks [0,1024): h1 rows (W_ei_ca3); last arrival runs top-2 + x_ca3 + compaction.
// Blocks [1024,2048): h3 rows (W_ei_ca1); last arrival runs top-100 + IS.
// Each half's select overlaps the other half's remaining matvec traffic.
__global__ __launch_bounds__(256) void matvec_dual_fused(
        const float* __restrict__ Wa, const float* __restrict__ Wb,
        const float* __restrict__ x) {
    int warp = threadIdx.x >> 5, lane = threadIdx.x & 31;
    int tid = threadIdx.x;
    bool is_h1 = blockIdx.x < 1024;
    int r = (is_h1 ? blockIdx.x : blockIdx.x - 1024) * 8 + warp;
    const float* W = is_h1 ? Wa : Wb;
    float* outv    = is_h1 ? g_h1 : g_h3;

    const float4* w4 = reinterpret_cast<const float4*>(W) + (size_t)r * (DIM_EI / 4);
    const float4* x4 = reinterpret_cast<const float4*>(x);
    float acc = 0.0f;
    #pragma unroll 8
    for (int i = lane; i < DIM_EI / 4; i += 32) {
        float4 w = __ldcs(&w4[i]);
        float4 v = __ldg(&x4[i]);
        acc += w.x * v.x + w.y * v.y + w.z * v.z + w.w * v.w;
    }
    #pragma unroll
    for (int o = 16; o; o >>= 1) acc += __shfl_down_sync(0xffffffffu, acc, o);
    if (lane == 0) {
        outv[r] = acc;
        __threadfence();           // release: row result visible before arrival
    }
    __syncthreads();

    __shared__ bool s_last;
    if (tid == 0) {
        unsigned* ctr = is_h1 ? &g_ctr_h1 : &g_ctr_h3;
        unsigned t = atomicAdd(ctr, 1u);
        s_last = (t == 1023u);
    }
    __syncthreads();
    if (!s_last) return;
    __threadfence();               // acquire

    if (is_h1) {
        // ---- top-2(h1) -> x_ca3 (masked) + deterministic compaction ----
        float th = kth_global_256(g_h1, DIM_CA3, 2);
        int base = tid * 32;       // contiguous segment per thread
        int cnt = 0;
        #pragma unroll 4
        for (int j = 0; j < 32; j++) {
            float xx = g_h1[base + j];
            int kp = (xx >= th);
            g_xca3[base + j] = kp ? sigm(BETA * (xx - th)) : 0.0f;
            cnt += kp;
        }
        // block exclusive scan over per-thread counts (index order preserved)
        __shared__ int wsum[8];
        int incl = cnt;
        #pragma unroll
        for (int o = 1; o < 32; o <<= 1) {
            int n = __shfl_up_sync(0xffffffffu, incl, o);
            if (lane >= o) incl += n;
        }
        if (lane == 31) wsum[warp] = incl;
        __syncthreads();
        if (tid == 0) {
            int s = 0;
            #pragma unroll
            for (int i = 0; i < 8; i++) { int c = wsum[i]; wsum[i] = s; s += c; }
            g_nnz_cnt = s;
            g_ctr_h1 = 0;          // self-reset for next graph replay
        }
        __syncthreads();
        int off = wsum[warp] + incl - cnt;
        for (int j = 0; j < 32 && off < g_nnz_cnt; j++) {
            float xx = g_h1[base + j];
            if (xx >= th) {
                g_nnz_idx[off] = base + j;
                g_nnz_val[off] = sigm(BETA * (xx - th));
                ++off;
            }
        }
    } else {
        // ---- top-100(h3) -> IS (masked) ----
        float th = kth_global_256(g_h3, DIM_CA1, 100);
        for (int i = tid; i < DIM_CA1; i += 256) {
            float xx = g_h3[i];
            g_IS[i] = (xx >= th) ? sigm(BETA * (xx - th)) : 0.0f;
        }
        if (tid == 0) g_ctr_h3 = 0;
    }
}

// ---------------- K2: fused h2 gather (~2 nnz) + top-100 + dense sigmoid ----------
__global__ void stageBC_kernel(const float* __restrict__ W3) {
    int cnt = g_nnz_cnt;
    int base = threadIdx.x * 8;
    float hv[8]; unsigned uv[8];
    #pragma unroll
    for (int r = 0; r < 8; r++) {
        size_t rowoff = (size_t)(base + r) * DIM_CA3;
        float acc = 0.0f;
        for (int k = 0; k < cnt; k++)
            acc += W3[rowoff + g_nnz_idx[k]] * g_nnz_val[k];
        hv[r] = acc; uv[r] = f2u(acc);
    }
    // 4-pass radix over register values (1024 threads, M=8)
    __shared__ unsigned s_hist[256];
    __shared__ int s_bin, s_k;
    unsigned prefix = 0; int k = 100;
    #pragma unroll
    for (int shift = 24; shift >= 0; shift -= 8) {
        if (threadIdx.x < 256) s_hist[threadIdx.x] = 0;
        __syncthreads();
        unsigned hi = (shift == 24) ? 0u : (0xFFFFFFFFu << (shift + 8));
        #pragma unroll
        for (int j = 0; j < 8; j++) {
            unsigned u = uv[j];
            if ((u & hi) == prefix) atomicAdd(&s_hist[(u >> shift) & 255], 1u);
        }
        __syncthreads();
        #pragma unroll
        for (int d = 1; d < 256; d <<= 1) {
            unsigned add = 0;
            if (threadIdx.x < 256)
                add = (threadIdx.x + d < 256) ? s_hist[threadIdx.x + d] : 0u;
            __syncthreads();
            if (threadIdx.x < 256) s_hist[threadIdx.x] += add;
            __syncthreads();
        }
        if (threadIdx.x < 256) {
            unsigned ge = s_hist[threadIdx.x];
            unsigned gt = (threadIdx.x == 255) ? 0u : s_hist[threadIdx.x + 1];
            if (ge >= (unsigned)k && gt < (unsigned)k) { s_bin = threadIdx.x; s_k = k - (int)gt; }
        }
        __syncthreads();
        prefix |= ((unsigned)s_bin) << shift;
        k = s_k;
        __syncthreads();
    }
    float th = u2f(prefix);
    #pragma unroll
    for (int r = 0; r < 8; r++)
        g_xca1[base + r] = sigm(BETA * (hv[r] - th));   // flag=False: no hard mask
}

// ---------------- K3: W_new = (1-IS*a)*W + a*IS*x_ca3^T ----------
__global__ void update_W_kernel(const float* __restrict__ W, float* __restrict__ out) {
    size_t idx = ((size_t)blockIdx.x * blockDim.x + threadIdx.x) * 4;
    int row = (int)(idx >> 13);          // / 8192
    int col = (int)(idx & (DIM_CA3 - 1));
    float s = g_IS[row];
    float a = 1.0f - s * ALPHA;
    float b = ALPHA * s;
    float4 w  = __ldcs(reinterpret_cast<const float4*>(W + idx));
    float4 xc = *reinterpret_cast<const float4*>(g_xca3 + col);
    float4 o;
    o.x = a * w.x + b * xc.x;
    o.y = a * w.y + b * xc.y;
    o.z = a * w.z + b * xc.z;
    o.w = a * w.w + b * xc.w;
    __stcs(reinterpret_cast<float4*>(out + idx), o);
}

// ---------------- K4: h4 = W_ca1_eo @ x_ca1; last block: top-50 + masked sigmoid ------
__global__ __launch_bounds__(256) void matvec_out_kernel(
        const float* __restrict__ W, float* __restrict__ out) {
    int warp = threadIdx.x >> 5, lane = threadIdx.x & 31;
    int tid = threadIdx.x;
    int row = blockIdx.x * 8 + warp;
    const float4* w4 = reinterpret_cast<const float4*>(W) + (size_t)row * (DIM_CA1 / 4);
    const float4* x4 = reinterpret_cast<const float4*>(g_xca1);
    float acc = 0.0f;
    #pragma unroll 8
    for (int i = lane; i < DIM_CA1 / 4; i += 32) {
        float4 w = __ldcs(&w4[i]);
        float4 v = __ldg(&x4[i]);
        acc += w.x * v.x + w.y * v.y + w.z * v.z + w.w * v.w;
    }
    #pragma unroll
    for (int o = 16; o; o >>= 1) acc += __shfl_down_sync(0xffffffffu, acc, o);
    if (lane == 0) {
        g_h4[row] = acc;
        __threadfence();
    }
    __syncthreads();
    __shared__ bool s_last;
    if (tid == 0) {
        unsigned t = atomicAdd(&g_ctr_out, 1u);
        s_last = (t == gridDim.x - 1);
    }
    __syncthreads();
    if (!s_last) return;
    __threadfence();
    float th = kth_global_256(g_h4, DIM_EO, 50);
    for (int i = tid; i < DIM_EO; i += 256) {
        float xx = g_h4[i];
        out[i] = (xx >= th) ? sigm(BETA * (xx - th)) : 0.0f;
    }
    if (tid == 0) g_ctr_out = 0;
}

// ---------------- launch: fork-join graph ----------------
extern "C" void kernel_launch(void* const* d_in, const int* in_sizes, int n_in,
                              void* d_out, int out_size) {
    const float* x_ei      = (const float*)d_in[0];
    const float* W_ei_ca3  = (const float*)d_in[1];
    const float* W_ei_ca1  = (const float*)d_in[2];
    const float* W_ca3_ca1 = (const float*)d_in[3];
    const float* W_ca1_eo  = (const float*)d_in[4];
    float* out = (float*)d_out;

    cudaStream_t s1;
    cudaStreamCreateWithFlags(&s1, cudaStreamNonBlocking);
    cudaEvent_t e_fork, e_join;
    cudaEventCreateWithFlags(&e_fork, cudaEventDisableTiming);
    cudaEventCreateWithFlags(&e_join, cudaEventDisableTiming);

    // matvecs + both selects in one launch (selects hidden under matvec tail)
    matvec_dual_fused<<<2048, 256>>>(W_ei_ca3, W_ei_ca1, x_ei);

    // fork: B-chain on s1, concurrent with update_W on stream0
    cudaEventRecord(e_fork, 0);
    cudaStreamWaitEvent(s1, e_fork, 0);

    stageBC_kernel<<<1, 1024, 0, s1>>>(W_ca3_ca1);
    matvec_out_kernel<<<DIM_EO / 8, 256, 0, s1>>>(W_ca1_eo, out);

    update_W_kernel<<<(unsigned)((size_t)DIM_CA1 * DIM_CA3 / 4 / 256), 256>>>(W_ca3_ca1, out + DIM_EO);

    // join
    cudaEventRecord(e_join, s1);
    cudaStreamWaitEvent(0, e_join, 0);

    cudaEventDestroy(e_fork);
    cudaEventDestroy(e_join);
    cudaStreamDestroy(s1);
}